// round 6
// baseline (speedup 1.0000x reference)
#include <cuda_runtime.h>
#include <cuda_bf16.h>

// Fused single-kernel deterministic reduction: out = sum(x) * a * b
// x: 8192*8192 fp32 (d_in[0]), a,b: scalar fp32 (d_in[1], d_in[2]).
//
// Grid = 152 SMs * 8 CTAs = 1216 CTAs of 256 threads: exactly one balanced
// wave on GB300 (every SM hosts 8 CTAs -> no BW-starved tail, unlike 1024).
// n4 = 2^24 float4. 311,296 threads * 53 iters = 16,498,688; the remaining
// 278,528 float4 are one predicated extra iteration for the low threads.

#define R_SMS     152
#define R_CTAS_PER_SM 8
#define R_BLOCKS  (R_SMS * R_CTAS_PER_SM)        // 1216
#define R_THREADS 256
#define R_NTHREADS (R_BLOCKS * R_THREADS)        // 311296
#define R_ITERS   53                              // uniform part
#define R_REM     (16777216 - R_NTHREADS * R_ITERS)  // 278528 extra float4

__device__ float g_partials[R_BLOCKS];
__device__ unsigned int g_count = 0;   // self-resetting: graph-replay safe

__device__ __forceinline__ float block_reduce(float s)
{
    #pragma unroll
    for (int o = 16; o > 0; o >>= 1)
        s += __shfl_xor_sync(0xffffffffu, s, o);

    __shared__ float sh[R_THREADS / 32];
    int lane = threadIdx.x & 31;
    int warp = threadIdx.x >> 5;
    if (lane == 0) sh[warp] = s;
    __syncthreads();

    if (warp == 0) {
        s = (lane < (R_THREADS / 32)) ? sh[lane] : 0.f;
        #pragma unroll
        for (int o = 16; o > 0; o >>= 1)
            s += __shfl_xor_sync(0xffffffffu, s, o);
    }
    return s;  // valid in warp 0 lane 0
}

__global__ __launch_bounds__(R_THREADS) void reduce_fused(
    const float4* __restrict__ x4,
    const float* __restrict__ a, const float* __restrict__ b,
    float* __restrict__ out)
{
    const unsigned idx    = blockIdx.x * R_THREADS + threadIdx.x;
    const unsigned stride = R_NTHREADS;

    float s0 = 0.f, s1 = 0.f, s2 = 0.f, s3 = 0.f;

    // Uniform, bounds-check-free mainloop: 53 coalesced LDG.128 per thread,
    // unrolled in batches for memory-level parallelism.
    #pragma unroll 8
    for (int j = 0; j < R_ITERS; j++) {
        float4 v = x4[idx + (unsigned)j * stride];
        s0 += v.x; s1 += v.y; s2 += v.z; s3 += v.w;
    }
    // Predicated remainder: contiguous final chunk.
    if (idx < (unsigned)R_REM) {
        float4 v = x4[idx + (unsigned)R_ITERS * stride];
        s0 += v.x; s1 += v.y; s2 += v.z; s3 += v.w;
    }

    float s = block_reduce((s0 + s1) + (s2 + s3));

    __shared__ bool is_last;
    if (threadIdx.x == 0) {
        g_partials[blockIdx.x] = s;
        __threadfence();
        unsigned int prev = atomicAdd(&g_count, 1u);
        is_last = (prev == (unsigned)(R_BLOCKS - 1));
    }
    __syncthreads();

    if (is_last) {
        // Deterministic final fold: fixed per-thread strided order.
        float t = 0.f;
        for (int i = threadIdx.x; i < R_BLOCKS; i += R_THREADS)
            t += g_partials[i];
        t = block_reduce(t);
        if (threadIdx.x == 0) {
            out[0] = t * a[0] * b[0];
            g_count = 0;   // reset for next graph replay
        }
    }
}

extern "C" void kernel_launch(void* const* d_in, const int* in_sizes, int n_in,
                              void* d_out, int out_size)
{
    const float4* x4 = (const float4*)d_in[0];
    const float* a   = (const float*)d_in[1];
    const float* b   = (const float*)d_in[2];
    float* out       = (float*)d_out;

    reduce_fused<<<R_BLOCKS, R_THREADS>>>(x4, a, b, out);
}